// round 1
// baseline (speedup 1.0000x reference)
#include <cuda_runtime.h>
#include <math.h>

// ---------------------------------------------------------------------------
// CausalSelfAttention: y = Attn(x W_QKV^T) W_O^T
// B=2, T=4096, D=512, H=8, d=64, fp32.
// Stage 1: qkv = x @ W_QKV^T            (8192 x 1536, K=512)
// Stage 2: flash attention (causal)     -> g_attn (8192 x 512)
// Stage 3: y = g_attn @ W_O^T           (8192 x 512, K=512)
// ---------------------------------------------------------------------------

#define BATCH 2
#define SEQ   4096
#define DMODEL 512
#define NHEADS 8
#define HDIM  64
#define ROWS  (BATCH * SEQ)          // 8192
#define QKVCOLS (3 * DMODEL)         // 1536

static __device__ float g_qkv[ROWS * QKVCOLS];   // ~50 MB scratch
static __device__ float g_attn[ROWS * DMODEL];   // ~16 MB scratch

// ---------------------------------------------------------------------------
// SGEMM: C[M,N] = A[M,K] @ B[N,K]^T   (both operands K-contiguous)
// 128x128 block tile, BK=8, 256 threads, 8x8 per-thread microtile.
// M, N multiples of 128; K multiple of 8 (holds for all our shapes).
// ---------------------------------------------------------------------------
__global__ __launch_bounds__(256, 2)
void gemm_abt_kernel(const float* __restrict__ A,
                     const float* __restrict__ B,
                     float* __restrict__ C,
                     int K, int N)
{
    __shared__ float As[8][128];
    __shared__ float Bs[8][128];

    const int tid = threadIdx.x;
    const int tx  = tid & 15;        // 0..15  -> n microtile
    const int ty  = tid >> 4;        // 0..15  -> m microtile
    const int m0  = blockIdx.y * 128;
    const int n0  = blockIdx.x * 128;

    const int lrow = tid >> 1;           // 0..127
    const int lk   = (tid & 1) * 4;      // 0 or 4

    const float* Aptr = A + (long long)(m0 + lrow) * K + lk;
    const float* Bptr = B + (long long)(n0 + lrow) * K + lk;

    float acc[8][8] = {};

    for (int k0 = 0; k0 < K; k0 += 8) {
        float4 av = *(const float4*)(Aptr + k0);
        float4 bv = *(const float4*)(Bptr + k0);
        __syncthreads();
        As[lk + 0][lrow] = av.x; As[lk + 1][lrow] = av.y;
        As[lk + 2][lrow] = av.z; As[lk + 3][lrow] = av.w;
        Bs[lk + 0][lrow] = bv.x; Bs[lk + 1][lrow] = bv.y;
        Bs[lk + 2][lrow] = bv.z; Bs[lk + 3][lrow] = bv.w;
        __syncthreads();

        #pragma unroll
        for (int k = 0; k < 8; k++) {
            float ar[8], br[8];
            *(float4*)&ar[0] = *(const float4*)&As[k][ty * 8];
            *(float4*)&ar[4] = *(const float4*)&As[k][ty * 8 + 4];
            *(float4*)&br[0] = *(const float4*)&Bs[k][tx * 8];
            *(float4*)&br[4] = *(const float4*)&Bs[k][tx * 8 + 4];
            #pragma unroll
            for (int i = 0; i < 8; i++)
                #pragma unroll
                for (int j = 0; j < 8; j++)
                    acc[i][j] += ar[i] * br[j];
        }
    }

    #pragma unroll
    for (int i = 0; i < 8; i++) {
        float* crow = C + (long long)(m0 + ty * 8 + i) * N + n0 + tx * 8;
        *(float4*)(crow)     = make_float4(acc[i][0], acc[i][1], acc[i][2], acc[i][3]);
        *(float4*)(crow + 4) = make_float4(acc[i][4], acc[i][5], acc[i][6], acc[i][7]);
    }
}

// ---------------------------------------------------------------------------
// Flash attention, fp32, causal.
// Grid: (64 q-tiles, B*H).  Block: 256 threads (16x16), 4x4 microtiles.
// smem: Qs[64][68] (pre-scaled), Kt[64][68] (d-major), Vs[64][68], Ps[64][68]
// ---------------------------------------------------------------------------
#define FPITCH 68
#define FLASH_SMEM (4 * 64 * FPITCH * 4)

__global__ __launch_bounds__(256)
void flash_attn_kernel(const float* __restrict__ qkv, float* __restrict__ out)
{
    extern __shared__ float sm[];
    float* Qs = sm;
    float* Kt = Qs + 64 * FPITCH;
    float* Vs = Kt + 64 * FPITCH;
    float* Ps = Vs + 64 * FPITCH;

    const int tid = threadIdx.x;
    const int tx  = tid & 15;
    const int ty  = tid >> 4;
    // reverse so the heaviest (longest-loop) tiles launch first
    const int qt  = (int)gridDim.x - 1 - (int)blockIdx.x;
    const int b   = blockIdx.y >> 3;
    const int h   = blockIdx.y & 7;
    const int q0  = qt * 64;
    const size_t base = (size_t)b * SEQ * QKVCOLS + (size_t)h * HDIM;

    // ---- load Q tile, pre-scaled by 1/sqrt(64) ----
    {
        const int row = tid >> 2;            // 0..63
        const int d0  = (tid & 3) * 16;      // 0,16,32,48
        const float* src = qkv + base + (size_t)(q0 + row) * QKVCOLS + d0;
        #pragma unroll
        for (int e = 0; e < 4; e++) {
            float4 v = *(const float4*)(src + e * 4);
            float* dst = &Qs[row * FPITCH + d0 + e * 4];
            dst[0] = v.x * 0.125f; dst[1] = v.y * 0.125f;
            dst[2] = v.z * 0.125f; dst[3] = v.w * 0.125f;
        }
    }

    float row_max[4], row_sum[4], acc[4][4];
    #pragma unroll
    for (int i = 0; i < 4; i++) {
        row_max[i] = -1e30f; row_sum[i] = 0.f;
        acc[i][0] = acc[i][1] = acc[i][2] = acc[i][3] = 0.f;
    }

    const int ntiles = qt + 1;
    for (int kt = 0; kt < ntiles; kt++) {
        const int k0 = kt * 64;
        __syncthreads();   // Ps/Kt/Vs from previous iter fully consumed

        // ---- load K (transposed: Kt[d][kc]) and V tiles ----
        {
            const int row = tid >> 2;
            const int d0  = (tid & 3) * 16;
            const float* ksrc = qkv + base + (size_t)(k0 + row) * QKVCOLS + DMODEL + d0;
            const float* vsrc = ksrc + DMODEL;
            #pragma unroll
            for (int e = 0; e < 4; e++) {
                float4 kv = *(const float4*)(ksrc + e * 4);
                Kt[(d0 + e * 4 + 0) * FPITCH + row] = kv.x;
                Kt[(d0 + e * 4 + 1) * FPITCH + row] = kv.y;
                Kt[(d0 + e * 4 + 2) * FPITCH + row] = kv.z;
                Kt[(d0 + e * 4 + 3) * FPITCH + row] = kv.w;
                float4 vv = *(const float4*)(vsrc + e * 4);
                *(float4*)&Vs[row * FPITCH + d0 + e * 4] = vv;
            }
        }
        __syncthreads();

        // ---- S = Qs @ Kt (already scaled) ----
        float s[4][4] = {};
        #pragma unroll 8
        for (int d = 0; d < 64; d++) {
            float4 kv = *(const float4*)&Kt[d * FPITCH + tx * 4];
            #pragma unroll
            for (int i = 0; i < 4; i++) {
                float qv = Qs[(ty * 4 + i) * FPITCH + d];
                s[i][0] += qv * kv.x; s[i][1] += qv * kv.y;
                s[i][2] += qv * kv.z; s[i][3] += qv * kv.w;
            }
        }

        // ---- causal mask (only the diagonal tile can violate) ----
        if (kt == ntiles - 1) {
            #pragma unroll
            for (int i = 0; i < 4; i++) {
                const int qi = q0 + ty * 4 + i;
                #pragma unroll
                for (int j = 0; j < 4; j++)
                    if (k0 + tx * 4 + j > qi) s[i][j] = -1e30f;
            }
        }

        // ---- online softmax (16-lane row groups) ----
        #pragma unroll
        for (int i = 0; i < 4; i++) {
            float mx = fmaxf(fmaxf(s[i][0], s[i][1]), fmaxf(s[i][2], s[i][3]));
            mx = fmaxf(mx, __shfl_xor_sync(0xffffffffu, mx, 1, 16));
            mx = fmaxf(mx, __shfl_xor_sync(0xffffffffu, mx, 2, 16));
            mx = fmaxf(mx, __shfl_xor_sync(0xffffffffu, mx, 4, 16));
            mx = fmaxf(mx, __shfl_xor_sync(0xffffffffu, mx, 8, 16));
            const float nm   = fmaxf(row_max[i], mx);
            const float corr = __expf(row_max[i] - nm);
            row_max[i] = nm;

            float p0 = __expf(s[i][0] - nm);
            float p1 = __expf(s[i][1] - nm);
            float p2 = __expf(s[i][2] - nm);
            float p3 = __expf(s[i][3] - nm);
            float* pr = &Ps[(ty * 4 + i) * FPITCH + tx * 4];
            pr[0] = p0; pr[1] = p1; pr[2] = p2; pr[3] = p3;

            float ts = (p0 + p1) + (p2 + p3);
            ts += __shfl_xor_sync(0xffffffffu, ts, 1, 16);
            ts += __shfl_xor_sync(0xffffffffu, ts, 2, 16);
            ts += __shfl_xor_sync(0xffffffffu, ts, 4, 16);
            ts += __shfl_xor_sync(0xffffffffu, ts, 8, 16);

            row_sum[i] = row_sum[i] * corr + ts;
            acc[i][0] *= corr; acc[i][1] *= corr;
            acc[i][2] *= corr; acc[i][3] *= corr;
        }
        __syncthreads();

        // ---- O += P @ V ----
        #pragma unroll 8
        for (int j = 0; j < 64; j++) {
            float4 v4 = *(const float4*)&Vs[j * FPITCH + tx * 4];
            #pragma unroll
            for (int i = 0; i < 4; i++) {
                float p = Ps[(ty * 4 + i) * FPITCH + j];
                acc[i][0] += p * v4.x; acc[i][1] += p * v4.y;
                acc[i][2] += p * v4.z; acc[i][3] += p * v4.w;
            }
        }
    }

    // ---- epilogue: normalize & store to [B,T,512] layout ----
    #pragma unroll
    for (int i = 0; i < 4; i++) {
        const float inv = 1.f / row_sum[i];
        const size_t o = ((size_t)b * SEQ + q0 + ty * 4 + i) * DMODEL
                       + (size_t)h * HDIM + tx * 4;
        *(float4*)&out[o] = make_float4(acc[i][0] * inv, acc[i][1] * inv,
                                        acc[i][2] * inv, acc[i][3] * inv);
    }
}

// ---------------------------------------------------------------------------
extern "C" void kernel_launch(void* const* d_in, const int* in_sizes, int n_in,
                              void* d_out, int out_size)
{
    const float* x    = (const float*)d_in[0];   // [2,4096,512]
    const float* wqkv = (const float*)d_in[1];   // [1536,512]
    const float* wo   = (const float*)d_in[2];   // [512,512]
    float* out        = (float*)d_out;           // [2,4096,512]

    float *qkvp, *attnp;
    cudaGetSymbolAddress((void**)&qkvp, g_qkv);
    cudaGetSymbolAddress((void**)&attnp, g_attn);

    cudaFuncSetAttribute(flash_attn_kernel,
                         cudaFuncAttributeMaxDynamicSharedMemorySize, FLASH_SMEM);

    // qkv = x @ W_QKV^T : M=8192, N=1536, K=512
    gemm_abt_kernel<<<dim3(QKVCOLS / 128, ROWS / 128), 256>>>(x, wqkv, qkvp, DMODEL, QKVCOLS);

    // causal flash attention
    flash_attn_kernel<<<dim3(SEQ / 64, BATCH * NHEADS), 256, FLASH_SMEM>>>(qkvp, attnp);

    // y = attn @ W_O^T : M=8192, N=512, K=512
    gemm_abt_kernel<<<dim3(DMODEL / 128, ROWS / 128), 256>>>(attnp, wo, out, DMODEL, DMODEL);
}

// round 2
// speedup vs baseline: 2.9998x; 2.9998x over previous
#include <cuda_runtime.h>
#include <math.h>

// ---------------------------------------------------------------------------
// CausalSelfAttention via TF32 tensor-core mma.sync (sm_103a)
// Stage 1: qkv = x @ W_QKV^T   (8192 x 1536, K=512)
// Stage 2: causal flash attention -> g_attn (8192 x 512)
// Stage 3: y = g_attn @ W_O^T  (8192 x 512, K=512)
// ---------------------------------------------------------------------------

#define BATCH 2
#define SEQ   4096
#define DMODEL 512
#define NHEADS 8
#define HDIM  64
#define ROWS  (BATCH * SEQ)
#define QKVCOLS (3 * DMODEL)

static __device__ float g_qkv[ROWS * QKVCOLS];
static __device__ float g_attn[ROWS * DMODEL];

__device__ __forceinline__ unsigned f2tf(float x) {
    unsigned r;
    asm("cvt.rna.tf32.f32 %0, %1;" : "=r"(r) : "f"(x));
    return r;
}

// D += A(16x8) * B(8x8), tf32 inputs, fp32 accumulate
__device__ __forceinline__ void mma8(float* c,
                                     unsigned a0, unsigned a1, unsigned a2, unsigned a3,
                                     unsigned b0, unsigned b1) {
    asm("mma.sync.aligned.m16n8k8.row.col.f32.tf32.tf32.f32 "
        "{%0,%1,%2,%3}, {%4,%5,%6,%7}, {%8,%9}, {%0,%1,%2,%3};"
        : "+f"(c[0]), "+f"(c[1]), "+f"(c[2]), "+f"(c[3])
        : "r"(a0), "r"(a1), "r"(a2), "r"(a3), "r"(b0), "r"(b1));
}

// ---------------------------------------------------------------------------
// TF32 GEMM: C[M,N] = A[M,K] @ B[N,K]^T. Block 128x128, 128 threads (4 warps),
// warp tile 64x64, BK=32. Smem pitch 36 -> conflict-free fragment LDS.
// ---------------------------------------------------------------------------
#define GP 36

__global__ __launch_bounds__(128)
void gemm_tf32(const float* __restrict__ A, const float* __restrict__ B,
               float* __restrict__ C, int K, int N)
{
    __shared__ unsigned As[128 * GP];
    __shared__ unsigned Bs[128 * GP];

    const int tid  = threadIdx.x;
    const int lane = tid & 31;
    const int wid  = tid >> 5;
    const int g    = lane >> 2;      // 0..7
    const int cc   = lane & 3;       // 0..3
    const int wm   = (wid & 1) * 64;
    const int wn   = (wid >> 1) * 64;
    const int m0   = blockIdx.y * 128;
    const int n0   = blockIdx.x * 128;

    float acc[4][8][4];
    #pragma unroll
    for (int mt = 0; mt < 4; mt++)
        #pragma unroll
        for (int nt = 0; nt < 8; nt++)
            #pragma unroll
            for (int j = 0; j < 4; j++) acc[mt][nt][j] = 0.f;

    for (int k0 = 0; k0 < K; k0 += 32) {
        __syncthreads();
        // stage A,B tiles (128x32 each), convert to tf32, conflict-free STS.128
        #pragma unroll
        for (int i = 0; i < 8; i++) {
            int idx = i * 128 + tid;
            int r   = idx >> 3;
            int c4  = (idx & 7) << 2;
            float4 av = *(const float4*)(A + (size_t)(m0 + r) * K + k0 + c4);
            *(uint4*)&As[r * GP + c4] =
                make_uint4(f2tf(av.x), f2tf(av.y), f2tf(av.z), f2tf(av.w));
            float4 bv = *(const float4*)(B + (size_t)(n0 + r) * K + k0 + c4);
            *(uint4*)&Bs[r * GP + c4] =
                make_uint4(f2tf(bv.x), f2tf(bv.y), f2tf(bv.z), f2tf(bv.w));
        }
        __syncthreads();

        #pragma unroll
        for (int ks = 0; ks < 4; ks++) {
            unsigned a[4][4], b[8][2];
            #pragma unroll
            for (int mt = 0; mt < 4; mt++) {
                const unsigned* p = &As[(wm + mt * 16) * GP + ks * 8];
                a[mt][0] = p[g * GP + cc];
                a[mt][1] = p[(g + 8) * GP + cc];
                a[mt][2] = p[g * GP + cc + 4];
                a[mt][3] = p[(g + 8) * GP + cc + 4];
            }
            #pragma unroll
            for (int nt = 0; nt < 8; nt++) {
                const unsigned* p = &Bs[(wn + nt * 8 + g) * GP + ks * 8];
                b[nt][0] = p[cc];
                b[nt][1] = p[cc + 4];
            }
            #pragma unroll
            for (int mt = 0; mt < 4; mt++)
                #pragma unroll
                for (int nt = 0; nt < 8; nt++)
                    mma8(acc[mt][nt], a[mt][0], a[mt][1], a[mt][2], a[mt][3],
                         b[nt][0], b[nt][1]);
        }
    }

    #pragma unroll
    for (int mt = 0; mt < 4; mt++) {
        int row = m0 + wm + mt * 16 + g;
        #pragma unroll
        for (int nt = 0; nt < 8; nt++) {
            int col = n0 + wn + nt * 8 + 2 * cc;
            *(float2*)&C[(size_t)row * N + col] =
                make_float2(acc[mt][nt][0], acc[mt][nt][1]);
            *(float2*)&C[(size_t)(row + 8) * N + col] =
                make_float2(acc[mt][nt][2], acc[mt][nt][3]);
        }
    }
}

// ---------------------------------------------------------------------------
// TF32 flash attention, causal. CTA: 128 threads (4 warps), q-tile 64 rows,
// warp handles 16 q-rows x full 64 kv-cols. Smem pitch 72 -> all fragment
// LDS conflict-free (Q/K: bank 8g+cc, V: bank 8cc+g, both injective).
// ---------------------------------------------------------------------------
#define AP 72
#define ASMEM (4 * 64 * AP * 4)

__global__ __launch_bounds__(128)
void flash_tf32(const float* __restrict__ qkv, float* __restrict__ out)
{
    extern __shared__ unsigned sm[];
    unsigned* Qs = sm;
    unsigned* Ks = Qs + 64 * AP;
    unsigned* Vs = Ks + 64 * AP;
    unsigned* Ps = Vs + 64 * AP;

    const int tid  = threadIdx.x;
    const int lane = tid & 31;
    const int w    = tid >> 5;
    const int g    = lane >> 2;
    const int cc   = lane & 3;
    const int qt   = (int)gridDim.x - 1 - (int)blockIdx.x;  // heavy tiles first
    const int b    = blockIdx.y >> 3;
    const int h    = blockIdx.y & 7;
    const int q0   = qt * 64;
    const size_t base = (size_t)b * SEQ * QKVCOLS + (size_t)h * HDIM;

    // stage Q tile (pre-scaled by 1/sqrt(64), tf32-truncated)
    #pragma unroll
    for (int i = 0; i < 8; i++) {
        int idx = i * 128 + tid;
        int r   = idx >> 4;
        int c4  = (idx & 15) << 2;
        float4 v = *(const float4*)(qkv + base + (size_t)(q0 + r) * QKVCOLS + c4);
        *(uint4*)&Qs[r * AP + c4] = make_uint4(
            f2tf(v.x * 0.125f), f2tf(v.y * 0.125f),
            f2tf(v.z * 0.125f), f2tf(v.w * 0.125f));
    }

    float rmax[2] = {-1e30f, -1e30f};
    float rsum[2] = {0.f, 0.f};
    float o[8][4];
    #pragma unroll
    for (int nt = 0; nt < 8; nt++)
        #pragma unroll
        for (int j = 0; j < 4; j++) o[nt][j] = 0.f;

    const int ntk = qt + 1;
    for (int kt = 0; kt < ntk; kt++) {
        const int k0 = kt * 64;
        __syncthreads();   // previous Ks/Vs/Ps fully consumed

        // stage K, V tiles (tf32)
        #pragma unroll
        for (int i = 0; i < 8; i++) {
            int idx = i * 128 + tid;
            int r   = idx >> 4;
            int c4  = (idx & 15) << 2;
            const float* kp = qkv + base + (size_t)(k0 + r) * QKVCOLS + DMODEL + c4;
            float4 kv = *(const float4*)kp;
            *(uint4*)&Ks[r * AP + c4] =
                make_uint4(f2tf(kv.x), f2tf(kv.y), f2tf(kv.z), f2tf(kv.w));
            float4 vv = *(const float4*)(kp + DMODEL);
            *(uint4*)&Vs[r * AP + c4] =
                make_uint4(f2tf(vv.x), f2tf(vv.y), f2tf(vv.z), f2tf(vv.w));
        }
        __syncthreads();

        // ---- S = Q @ K^T  (warp: 16 x 64) ----
        float s[8][4];
        #pragma unroll
        for (int nt = 0; nt < 8; nt++)
            #pragma unroll
            for (int j = 0; j < 4; j++) s[nt][j] = 0.f;

        #pragma unroll
        for (int ks = 0; ks < 8; ks++) {
            const unsigned* qp = &Qs[(w * 16) * AP + ks * 8];
            unsigned a0 = qp[g * AP + cc];
            unsigned a1 = qp[(g + 8) * AP + cc];
            unsigned a2 = qp[g * AP + cc + 4];
            unsigned a3 = qp[(g + 8) * AP + cc + 4];
            #pragma unroll
            for (int nt = 0; nt < 8; nt++) {
                const unsigned* kp2 = &Ks[(nt * 8 + g) * AP + ks * 8];
                mma8(s[nt], a0, a1, a2, a3, kp2[cc], kp2[cc + 4]);
            }
        }

        // ---- causal mask (diagonal tile only) ----
        if (kt == ntk - 1) {
            #pragma unroll
            for (int nt = 0; nt < 8; nt++) {
                int col = k0 + nt * 8 + 2 * cc;
                int r0  = q0 + w * 16 + g;
                int r1  = r0 + 8;
                if (col     > r0) s[nt][0] = -1e30f;
                if (col + 1 > r0) s[nt][1] = -1e30f;
                if (col     > r1) s[nt][2] = -1e30f;
                if (col + 1 > r1) s[nt][3] = -1e30f;
            }
        }

        // ---- online softmax: rows g and g+8, quad-shuffle reductions ----
        #pragma unroll
        for (int half = 0; half < 2; half++) {
            float mx = -1e30f;
            #pragma unroll
            for (int nt = 0; nt < 8; nt++)
                mx = fmaxf(mx, fmaxf(s[nt][half * 2], s[nt][half * 2 + 1]));
            mx = fmaxf(mx, __shfl_xor_sync(0xffffffffu, mx, 1));
            mx = fmaxf(mx, __shfl_xor_sync(0xffffffffu, mx, 2));
            const float nm   = fmaxf(rmax[half], mx);
            const float corr = __expf(rmax[half] - nm);
            rmax[half] = nm;

            float sum = 0.f;
            unsigned* pr = &Ps[(w * 16 + g + half * 8) * AP];
            #pragma unroll
            for (int nt = 0; nt < 8; nt++) {
                float p0 = __expf(s[nt][half * 2]     - nm);
                float p1 = __expf(s[nt][half * 2 + 1] - nm);
                sum += p0 + p1;
                *(uint2*)&pr[nt * 8 + 2 * cc] = make_uint2(f2tf(p0), f2tf(p1));
                o[nt][half * 2]     *= corr;
                o[nt][half * 2 + 1] *= corr;
            }
            sum += __shfl_xor_sync(0xffffffffu, sum, 1);
            sum += __shfl_xor_sync(0xffffffffu, sum, 2);
            rsum[half] = rsum[half] * corr + sum;
        }
        __syncwarp();   // P STS -> P LDS within warp

        // ---- O += P @ V ----
        #pragma unroll
        for (int ks = 0; ks < 8; ks++) {
            const unsigned* pp = &Ps[(w * 16) * AP + ks * 8];
            unsigned a0 = pp[g * AP + cc];
            unsigned a1 = pp[(g + 8) * AP + cc];
            unsigned a2 = pp[g * AP + cc + 4];
            unsigned a3 = pp[(g + 8) * AP + cc + 4];
            #pragma unroll
            for (int nt = 0; nt < 8; nt++) {
                const unsigned* vp = &Vs[(ks * 8) * AP + nt * 8 + g];
                mma8(o[nt], a0, a1, a2, a3, vp[cc * AP], vp[(cc + 4) * AP]);
            }
        }
    }

    // ---- epilogue: normalize, store to [B,T,512] ----
    const float inv0 = 1.f / rsum[0];
    const float inv1 = 1.f / rsum[1];
    const size_t orow = (size_t)b * SEQ + q0 + w * 16 + g;
    #pragma unroll
    for (int nt = 0; nt < 8; nt++) {
        size_t off = orow * DMODEL + h * HDIM + nt * 8 + 2 * cc;
        *(float2*)&out[off] = make_float2(o[nt][0] * inv0, o[nt][1] * inv0);
        *(float2*)&out[off + 8 * DMODEL] = make_float2(o[nt][2] * inv1, o[nt][3] * inv1);
    }
}

// ---------------------------------------------------------------------------
extern "C" void kernel_launch(void* const* d_in, const int* in_sizes, int n_in,
                              void* d_out, int out_size)
{
    const float* x    = (const float*)d_in[0];
    const float* wqkv = (const float*)d_in[1];
    const float* wo   = (const float*)d_in[2];
    float* out        = (float*)d_out;

    float *qkvp, *attnp;
    cudaGetSymbolAddress((void**)&qkvp, g_qkv);
    cudaGetSymbolAddress((void**)&attnp, g_attn);

    cudaFuncSetAttribute(flash_tf32,
                         cudaFuncAttributeMaxDynamicSharedMemorySize, ASMEM);

    // qkv = x @ W_QKV^T : M=8192, N=1536, K=512
    gemm_tf32<<<dim3(QKVCOLS / 128, ROWS / 128), 128>>>(x, wqkv, qkvp, DMODEL, QKVCOLS);

    // causal flash attention
    flash_tf32<<<dim3(SEQ / 64, BATCH * NHEADS), 128, ASMEM>>>(qkvp, attnp);

    // y = attn @ W_O^T : M=8192, N=512, K=512
    gemm_tf32<<<dim3(DMODEL / 128, ROWS / 128), 128>>>(attnp, wo, out, DMODEL, DMODEL);
}